// round 3
// baseline (speedup 1.0000x reference)
#include <cuda_runtime.h>

#define NN   50000
#define EE   800000
#define DIN  128
#define HC   128
#define CCH  64
#define ED   32
#define NPB  8

// ---- scratch (static __device__ arrays; no allocations allowed) ----
__device__ float g_q[NN * HC];
__device__ float g_k[NN * HC];
__device__ float g_v[NN * HC];
__device__ float g_qwe[NN * 2 * ED];   // [n][h][d] : q[n,h,:] . We[d, h*64 + :]
__device__ int   g_deg[NN];
__device__ int   g_off[NN + 1];
__device__ int   g_cur[NN];
__device__ int   g_srcs[EE];
__device__ int   g_eids[EE];

// ---------------- node projections: q,k,v + skip->out ----------------
__global__ void proj_kernel(const float* __restrict__ x,
                            const float* __restrict__ Wq, const float* __restrict__ bq,
                            const float* __restrict__ Wk, const float* __restrict__ bk,
                            const float* __restrict__ Wv, const float* __restrict__ bv,
                            const float* __restrict__ Wskip, const float* __restrict__ bskip,
                            float* __restrict__ out)
{
    __shared__ float xs[NPB][DIN];
    const int n0 = blockIdx.x * NPB;
    const int c  = threadIdx.x;   // 0..127 output channel

    #pragma unroll
    for (int i = 0; i < NPB; i++) {
        int n = n0 + i;
        xs[i][c] = (n < NN) ? x[n * DIN + c] : 0.f;
    }
    __syncthreads();

    float aq[NPB], ak[NPB], av[NPB], as_[NPB];
    #pragma unroll
    for (int i = 0; i < NPB; i++) { aq[i] = 0.f; ak[i] = 0.f; av[i] = 0.f; as_[i] = 0.f; }

    for (int k = 0; k < DIN; k++) {
        float wq = Wq[k * HC + c];
        float wk = Wk[k * HC + c];
        float wv = Wv[k * HC + c];
        float ws = Wskip[k * HC + c];
        #pragma unroll
        for (int i = 0; i < NPB; i++) {
            float xv = xs[i][k];
            aq[i]  += xv * wq;
            ak[i]  += xv * wk;
            av[i]  += xv * wv;
            as_[i] += xv * ws;
        }
    }

    const float Bq = bq[c], Bk = bk[c], Bv = bv[c], Bs = bskip[c];
    #pragma unroll
    for (int i = 0; i < NPB; i++) {
        int n = n0 + i;
        if (n >= NN) break;
        g_q[n * HC + c] = aq[i] + Bq;
        g_k[n * HC + c] = ak[i] + Bk;
        g_v[n * HC + c] = av[i] + Bv;
        out[n * HC + c] = as_[i] + Bs;   // skip connection initializes output
    }
}

// ---------------- qWe[n,h,d] = sum_c q[n,h,c] * We[d, h*64+c] ----------------
__global__ void qwe_kernel(const float* __restrict__ We)
{
    int idx = blockIdx.x * blockDim.x + threadIdx.x;
    if (idx >= NN * 2 * ED) return;
    int n  = idx >> 6;
    int hd = idx & 63;
    int h  = hd >> 5;
    const int d = hd & 31;
    const float* qr = &g_q[n * HC + h * CCH];
    const float* wr = &We[d * HC + h * CCH];
    float s = 0.f;
    #pragma unroll
    for (int cc = 0; cc < CCH; cc++) s += qr[cc] * wr[cc];
    g_qwe[idx] = s;
}

// ---------------- CSR build: zero -> histogram -> scan -> scatter ----------------
__global__ void zero_deg_kernel()
{
    int i = blockIdx.x * blockDim.x + threadIdx.x;
    if (i < NN) g_deg[i] = 0;
}

__global__ void hist_kernel(const int* __restrict__ ei)
{
    int e = blockIdx.x * blockDim.x + threadIdx.x;
    if (e < EE) atomicAdd(&g_deg[ei[EE + e]], 1);
}

__global__ void scan_kernel()
{
    __shared__ int sums[1024];
    const int t  = threadIdx.x;
    const int CH = (NN + 1023) / 1024;
    const int base = t * CH;
    int s = 0;
    for (int i = 0; i < CH; i++) {
        int j = base + i;
        if (j < NN) s += g_deg[j];
    }
    sums[t] = s;
    __syncthreads();
    for (int off = 1; off < 1024; off <<= 1) {
        int v = 0;
        if (t >= off) v = sums[t - off];
        __syncthreads();
        if (t >= off) sums[t] += v;
        __syncthreads();
    }
    int run = sums[t] - s;   // exclusive prefix
    for (int i = 0; i < CH; i++) {
        int j = base + i;
        if (j < NN) {
            g_off[j] = run;
            g_cur[j] = run;
            run += g_deg[j];
        }
    }
    if (t == 1023) g_off[NN] = sums[1023];
}

__global__ void scatter_kernel(const int* __restrict__ ei)
{
    int e = blockIdx.x * blockDim.x + threadIdx.x;
    if (e >= EE) return;
    int d = ei[EE + e];
    int p = atomicAdd(&g_cur[d], 1);
    g_srcs[p] = ei[e];
    g_eids[p] = e;
}

// ---------------- aggregation: one warp per destination node ----------------
// Single pass (max-free softmax): accumulate s=exp(alpha), s*v[src], s*A, sum(s);
// divide once at the end. Edge-feature terms folded via linearity:
//   alpha edge term = qWe[n,h,:] . A[e,:]
//   output edge term = (sum_e s*A[e,:]) @ We_h
__global__ void agg_kernel(const float* __restrict__ edge_attr,
                           const float* __restrict__ We,
                           float* __restrict__ out)
{
    const int gw   = (blockIdx.x * blockDim.x + threadIdx.x) >> 5;
    const int lane = threadIdx.x & 31;
    __shared__ float swa[8][64];
    if (gw >= NN) return;
    const int n = gw;

    const int beg = g_off[n];
    const int end = g_off[n + 1];

    const float4 qv = *(const float4*)&g_q[n * HC + lane * 4];
    const float qw0 = g_qwe[n * 64 + lane];
    const float qw1 = g_qwe[n * 64 + 32 + lane];

    float a0 = 0.f, a1 = 0.f, a2 = 0.f, a3 = 0.f;
    float wa0 = 0.f, wa1 = 0.f, den0 = 0.f, den1 = 0.f;

    for (int i = beg; i < end; i++) {
        const int s   = g_srcs[i];
        const int eid = g_eids[i];

        const float4 kv = *(const float4*)&g_k[s * HC + lane * 4];
        float pd = qv.x * kv.x + qv.y * kv.y + qv.z * kv.z + qv.w * kv.w;
        // reduce within each 16-lane half (head0 = lanes 0-15, head1 = 16-31)
        pd += __shfl_xor_sync(0xffffffffu, pd, 8);
        pd += __shfl_xor_sync(0xffffffffu, pd, 4);
        pd += __shfl_xor_sync(0xffffffffu, pd, 2);
        pd += __shfl_xor_sync(0xffffffffu, pd, 1);
        const float dk0 = __shfl_sync(0xffffffffu, pd, 0);
        const float dk1 = __shfl_sync(0xffffffffu, pd, 16);

        const float av = edge_attr[eid * ED + lane];  // lane = d index
        float t0 = av * qw0;
        float t1 = av * qw1;
        #pragma unroll
        for (int off = 16; off; off >>= 1) {
            t0 += __shfl_xor_sync(0xffffffffu, t0, off);
            t1 += __shfl_xor_sync(0xffffffffu, t1, off);
        }

        const float s0 = __expf((dk0 + t0) * 0.125f);
        const float s1 = __expf((dk1 + t1) * 0.125f);
        den0 += s0;
        den1 += s1;

        const float4 vv = *(const float4*)&g_v[s * HC + lane * 4];
        const float sh = (lane < 16) ? s0 : s1;
        a0 += sh * vv.x; a1 += sh * vv.y; a2 += sh * vv.z; a3 += sh * vv.w;

        wa0 += s0 * av;
        wa1 += s1 * av;
    }

    const int w = threadIdx.x >> 5;
    swa[w][lane]      = wa0;
    swa[w][32 + lane] = wa1;
    __syncwarp();

    const float den = ((lane < 16) ? den0 : den1) + 1e-16f;
    const float inv = 1.0f / den;

    const int cbase = lane * 4;
    const int h = lane >> 4;
    const float* wap = &swa[w][h * 32];
    float accs[4] = { a0, a1, a2, a3 };
    float r[4];
    #pragma unroll
    for (int j = 0; j < 4; j++) {
        const int ccol = cbase + j;
        float ws = 0.f;
        #pragma unroll
        for (int d = 0; d < ED; d++) ws += wap[d] * We[d * HC + ccol];
        r[j] = (accs[j] + ws) * inv;
    }

    float4 o = *(float4*)&out[n * HC + cbase];
    o.x += r[0]; o.y += r[1]; o.z += r[2]; o.w += r[3];
    *(float4*)&out[n * HC + cbase] = o;
}

// ---------------- launch ----------------
extern "C" void kernel_launch(void* const* d_in, const int* in_sizes, int n_in,
                              void* d_out, int out_size)
{
    const float* x     = (const float*)d_in[0];
    const int*   ei    = (const int*)  d_in[1];
    const float* ea    = (const float*)d_in[2];
    const float* Wq    = (const float*)d_in[3];
    const float* bq    = (const float*)d_in[4];
    const float* Wk    = (const float*)d_in[5];
    const float* bk    = (const float*)d_in[6];
    const float* Wv    = (const float*)d_in[7];
    const float* bv    = (const float*)d_in[8];
    const float* We    = (const float*)d_in[9];
    const float* Wskip = (const float*)d_in[10];
    const float* bskip = (const float*)d_in[11];
    float* out = (float*)d_out;

    proj_kernel<<<(NN + NPB - 1) / NPB, 128>>>(x, Wq, bq, Wk, bk, Wv, bv, Wskip, bskip, out);
    qwe_kernel<<<(NN * 64 + 255) / 256, 256>>>(We);
    zero_deg_kernel<<<(NN + 255) / 256, 256>>>();
    hist_kernel<<<(EE + 255) / 256, 256>>>(ei);
    scan_kernel<<<1, 1024>>>();
    scatter_kernel<<<(EE + 255) / 256, 256>>>(ei);
    agg_kernel<<<(NN * 32 + 255) / 256, 256>>>(ea, We, out);
}

// round 5
// speedup vs baseline: 2.1087x; 2.1087x over previous
#include <cuda_runtime.h>

#define NN   50000
#define EE   800000
#define DIN  128
#define HC   128
#define CCH  64
#define ED   32
#define NPB  8
#define QNB  8

// ---- scratch (static __device__ arrays; no allocations allowed) ----
__device__ float g_q[NN * HC];
__device__ float g_k[NN * HC];
__device__ float g_v[NN * HC];
__device__ float g_qwe[NN * 2 * ED];   // [n][h][d] : q[n,h,:] . We[d, h*64 + :]
__device__ int   g_deg[NN];
__device__ int   g_off[NN + 1];
__device__ int   g_cur[NN];
__device__ int   g_srcs[EE];
__device__ int   g_eids[EE];

// ---------------- node projections: q,k,v + skip->out ----------------
__global__ void proj_kernel(const float* __restrict__ x,
                            const float* __restrict__ Wq, const float* __restrict__ bq,
                            const float* __restrict__ Wk, const float* __restrict__ bk,
                            const float* __restrict__ Wv, const float* __restrict__ bv,
                            const float* __restrict__ Wskip, const float* __restrict__ bskip,
                            float* __restrict__ out)
{
    __shared__ float xs[NPB][DIN];
    const int n0 = blockIdx.x * NPB;
    const int c  = threadIdx.x;   // 0..127 output channel

    #pragma unroll
    for (int i = 0; i < NPB; i++) {
        int n = n0 + i;
        xs[i][c] = (n < NN) ? x[n * DIN + c] : 0.f;
    }
    __syncthreads();

    float aq[NPB], ak[NPB], av[NPB], as_[NPB];
    #pragma unroll
    for (int i = 0; i < NPB; i++) { aq[i] = 0.f; ak[i] = 0.f; av[i] = 0.f; as_[i] = 0.f; }

    for (int k = 0; k < DIN; k++) {
        float wq = Wq[k * HC + c];
        float wk = Wk[k * HC + c];
        float wv = Wv[k * HC + c];
        float ws = Wskip[k * HC + c];
        #pragma unroll
        for (int i = 0; i < NPB; i++) {
            float xv = xs[i][k];
            aq[i]  += xv * wq;
            ak[i]  += xv * wk;
            av[i]  += xv * wv;
            as_[i] += xv * ws;
        }
    }

    const float Bq = bq[c], Bk = bk[c], Bv = bv[c], Bs = bskip[c];
    #pragma unroll
    for (int i = 0; i < NPB; i++) {
        int n = n0 + i;
        if (n >= NN) break;
        g_q[n * HC + c] = aq[i] + Bq;
        g_k[n * HC + c] = ak[i] + Bk;
        g_v[n * HC + c] = av[i] + Bv;
        out[n * HC + c] = as_[i] + Bs;   // skip connection initializes output
    }
}

// ---------------- qWe[n,h,d] = sum_c q[n,h,c] * We[d, h*64+c] ----------------
// Smem-staged version: We transposed into WeT[hc][d] (row pad 33 -> conflict-free
// column access), q tiled per block. Replaces the old strided-LDG version whose
// lane-varying 512B-stride global reads caused 32 L1tex wavefronts per load
// (~0.8 ms total).
__global__ void qwe_kernel(const float* __restrict__ We)
{
    __shared__ float WeT[128][33];    // [hc][d], padded
    __shared__ float qs[QNB][128];
    const int tid = threadIdx.x;      // 256 threads

    for (int idx = tid; idx < 32 * 128; idx += 256) {
        int d  = idx >> 7;
        int hc = idx & 127;
        WeT[hc][d] = We[idx];         // coalesced read, conflict-free write
    }
    const int n0 = blockIdx.x * QNB;
    for (int idx = tid; idx < QNB * 128; idx += 256) {
        int nl = idx >> 7;
        int n  = n0 + nl;
        qs[nl][idx & 127] = (n < NN) ? g_q[n * HC + (idx & 127)] : 0.f;
    }
    __syncthreads();

    const int d  = tid & 31;          // lane = d -> WeT row reads conflict-free
    const int nl = tid >> 5;          // warp-uniform -> qs reads broadcast
    float a0 = 0.f, a1 = 0.f;
    #pragma unroll
    for (int cc = 0; cc < CCH; cc++) {
        a0 += qs[nl][cc]       * WeT[cc][d];
        a1 += qs[nl][64 + cc]  * WeT[64 + cc][d];
    }
    const int n = n0 + nl;
    if (n < NN) {
        g_qwe[n * 64 + d]      = a0;
        g_qwe[n * 64 + 32 + d] = a1;
    }
}

// ---------------- CSR build: zero -> histogram -> scan -> scatter ----------------
__global__ void zero_deg_kernel()
{
    int i = blockIdx.x * blockDim.x + threadIdx.x;
    if (i < NN) g_deg[i] = 0;
}

__global__ void hist_kernel(const int* __restrict__ ei)
{
    int e = blockIdx.x * blockDim.x + threadIdx.x;
    if (e < EE) atomicAdd(&g_deg[ei[EE + e]], 1);
}

// Tile-looped coalesced block scan (1 block, 1024 threads).
__global__ void scan_kernel()
{
    const int tid  = threadIdx.x;
    const int lane = tid & 31;
    const int wid  = tid >> 5;
    __shared__ int wsum[32];
    __shared__ int s_carry;
    if (tid == 0) s_carry = 0;
    __syncthreads();

    for (int base = 0; base < NN; base += 1024) {
        int i = base + tid;
        int v = (i < NN) ? g_deg[i] : 0;     // coalesced

        // inclusive warp scan
        int x = v;
        #pragma unroll
        for (int o = 1; o < 32; o <<= 1) {
            int y = __shfl_up_sync(0xffffffffu, x, o);
            if (lane >= o) x += y;
        }
        if (lane == 31) wsum[wid] = x;
        __syncthreads();
        if (wid == 0) {
            int s = wsum[lane];
            #pragma unroll
            for (int o = 1; o < 32; o <<= 1) {
                int y = __shfl_up_sync(0xffffffffu, s, o);
                if (lane >= o) s += y;
            }
            wsum[lane] = s;
        }
        __syncthreads();
        int warp_off = (wid > 0) ? wsum[wid - 1] : 0;
        int excl = s_carry + warp_off + x - v;
        if (i < NN) { g_off[i] = excl; g_cur[i] = excl; }   // coalesced
        __syncthreads();
        if (tid == 1023) s_carry += warp_off + x;   // block total
        __syncthreads();
    }
    if (tid == 0) g_off[NN] = s_carry;
}

__global__ void scatter_kernel(const int* __restrict__ ei)
{
    int e = blockIdx.x * blockDim.x + threadIdx.x;
    if (e >= EE) return;
    int d = ei[EE + e];
    int p = atomicAdd(&g_cur[d], 1);
    g_srcs[p] = ei[e];
    g_eids[p] = e;
}

// ---------------- aggregation: one warp per destination node ----------------
// Single pass (max-free softmax): accumulate s=exp(alpha), s*v[src], s*A, sum(s);
// divide once at the end. Edge-feature terms folded via linearity:
//   alpha edge term = qWe[n,h,:] . A[e,:]
//   output edge term = (sum_e s*A[e,:]) @ We_h
__global__ void agg_kernel(const float* __restrict__ edge_attr,
                           const float* __restrict__ We,
                           float* __restrict__ out)
{
    const int gw   = (blockIdx.x * blockDim.x + threadIdx.x) >> 5;
    const int lane = threadIdx.x & 31;
    __shared__ float swa[8][64];
    if (gw >= NN) return;
    const int n = gw;

    const int beg = g_off[n];
    const int end = g_off[n + 1];

    const float4 qv = *(const float4*)&g_q[n * HC + lane * 4];
    const float qw0 = g_qwe[n * 64 + lane];
    const float qw1 = g_qwe[n * 64 + 32 + lane];

    float a0 = 0.f, a1 = 0.f, a2 = 0.f, a3 = 0.f;
    float wa0 = 0.f, wa1 = 0.f, den0 = 0.f, den1 = 0.f;

    for (int i = beg; i < end; i++) {
        const int s   = g_srcs[i];
        const int eid = g_eids[i];

        const float4 kv = *(const float4*)&g_k[s * HC + lane * 4];
        float pd = qv.x * kv.x + qv.y * kv.y + qv.z * kv.z + qv.w * kv.w;
        // reduce within each 16-lane half (head0 = lanes 0-15, head1 = 16-31)
        pd += __shfl_xor_sync(0xffffffffu, pd, 8);
        pd += __shfl_xor_sync(0xffffffffu, pd, 4);
        pd += __shfl_xor_sync(0xffffffffu, pd, 2);
        pd += __shfl_xor_sync(0xffffffffu, pd, 1);
        const float dk0 = __shfl_sync(0xffffffffu, pd, 0);
        const float dk1 = __shfl_sync(0xffffffffu, pd, 16);

        const float av = edge_attr[eid * ED + lane];  // lane = d index
        float t0 = av * qw0;
        float t1 = av * qw1;
        #pragma unroll
        for (int off = 16; off; off >>= 1) {
            t0 += __shfl_xor_sync(0xffffffffu, t0, off);
            t1 += __shfl_xor_sync(0xffffffffu, t1, off);
        }

        const float s0 = __expf((dk0 + t0) * 0.125f);
        const float s1 = __expf((dk1 + t1) * 0.125f);
        den0 += s0;
        den1 += s1;

        const float4 vv = *(const float4*)&g_v[s * HC + lane * 4];
        const float sh = (lane < 16) ? s0 : s1;
        a0 += sh * vv.x; a1 += sh * vv.y; a2 += sh * vv.z; a3 += sh * vv.w;

        wa0 += s0 * av;
        wa1 += s1 * av;
    }

    const int w = threadIdx.x >> 5;
    swa[w][lane]      = wa0;
    swa[w][32 + lane] = wa1;
    __syncwarp();

    const float den = ((lane < 16) ? den0 : den1) + 1e-16f;
    const float inv = 1.0f / den;

    const int cbase = lane * 4;
    const int h = lane >> 4;
    const float* wap = &swa[w][h * 32];
    float accs[4] = { a0, a1, a2, a3 };
    float r[4];
    #pragma unroll
    for (int j = 0; j < 4; j++) {
        const int ccol = cbase + j;
        float ws = 0.f;
        #pragma unroll
        for (int d = 0; d < ED; d++) ws += wap[d] * We[d * HC + ccol];
        r[j] = (accs[j] + ws) * inv;
    }

    float4 o = *(float4*)&out[n * HC + cbase];
    o.x += r[0]; o.y += r[1]; o.z += r[2]; o.w += r[3];
    *(float4*)&out[n * HC + cbase] = o;
}

// ---------------- launch ----------------
extern "C" void kernel_launch(void* const* d_in, const int* in_sizes, int n_in,
                              void* d_out, int out_size)
{
    const float* x     = (const float*)d_in[0];
    const int*   ei    = (const int*)  d_in[1];
    const float* ea    = (const float*)d_in[2];
    const float* Wq    = (const float*)d_in[3];
    const float* bq    = (const float*)d_in[4];
    const float* Wk    = (const float*)d_in[5];
    const float* bk    = (const float*)d_in[6];
    const float* Wv    = (const float*)d_in[7];
    const float* bv    = (const float*)d_in[8];
    const float* We    = (const float*)d_in[9];
    const float* Wskip = (const float*)d_in[10];
    const float* bskip = (const float*)d_in[11];
    float* out = (float*)d_out;

    proj_kernel<<<(NN + NPB - 1) / NPB, 128>>>(x, Wq, bq, Wk, bk, Wv, bv, Wskip, bskip, out);
    qwe_kernel<<<(NN + QNB - 1) / QNB, 256>>>(We);
    zero_deg_kernel<<<(NN + 255) / 256, 256>>>();
    hist_kernel<<<(EE + 255) / 256, 256>>>(ei);
    scan_kernel<<<1, 1024>>>();
    scatter_kernel<<<(EE + 255) / 256, 256>>>(ei);
    agg_kernel<<<(NN * 32 + 255) / 256, 256>>>(ea, We, out);
}

// round 8
// speedup vs baseline: 2.4902x; 1.1809x over previous
#include <cuda_runtime.h>
#include <cuda_bf16.h>
#include <cstdint>

#define NN   50000
#define NPAD 50048
#define EE   800000
#define HC   128
#define CCH  64
#define ED   32
#define QNB  8

// ---- scratch (static __device__ arrays; no allocations allowed) ----
__device__ __align__(256) __nv_bfloat16 g_xh[NPAD * 128];
__device__ __align__(256) __nv_bfloat16 g_xl[NPAD * 128];
__device__ __align__(256) __nv_bfloat16 g_Bh[512 * 128];   // [out_col][k] transposed split weights
__device__ __align__(256) __nv_bfloat16 g_Bl[512 * 128];
__device__ float g_q[NN * HC];
__device__ float g_k[NN * HC];
__device__ float g_v[NN * HC];
__device__ float g_qwe[NN * 2 * ED];
__device__ int   g_deg[NN];
__device__ int   g_off[NN + 1];
__device__ int   g_cur[NN];
__device__ int   g_srcs[EE];
__device__ int   g_eids[EE];

// ================= prep: split-bf16 conversion =================
__global__ void prep_x_kernel(const float* __restrict__ x)
{
    int idx = blockIdx.x * blockDim.x + threadIdx.x;
    if (idx >= NPAD * 128) return;
    float v = (idx < NN * 128) ? x[idx] : 0.f;
    __nv_bfloat16 hi = __float2bfloat16(v);
    g_xh[idx] = hi;
    g_xl[idx] = __float2bfloat16(v - __bfloat162float(hi));
}

// g_B*[n][k] = split(W_m[k][col]),  n = m*128+col, m in {q,k,v,skip}
__global__ void prep_w_kernel(const float* __restrict__ Wq, const float* __restrict__ Wk,
                              const float* __restrict__ Wv, const float* __restrict__ Wskip)
{
    int idx = blockIdx.x * blockDim.x + threadIdx.x;
    if (idx >= 512 * 128) return;
    int n = idx >> 7, k = idx & 127;
    int m = n >> 7, col = n & 127;
    const float* W = (m == 0) ? Wq : (m == 1) ? Wk : (m == 2) ? Wv : Wskip;
    float v = W[k * 128 + col];
    __nv_bfloat16 hi = __float2bfloat16(v);
    g_Bh[idx] = hi;
    g_Bl[idx] = __float2bfloat16(v - __bfloat162float(hi));
}

// ================= fused projection GEMM via mma.sync (HMMA bf16) =================
// D[128 rows, 128 cols] per CTA; grid = (NPAD/128, 4); blockIdx.y selects {q,k,v,skip}.
// Split-bf16: D = xh@Bh + xl@Bh + xh@Bl  (fp32 accum in registers)
#define PA 136                      // smem pitch (bf16 elems): 68 words/row -> conflict-free frags
#define A_TILE_B  (128 * PA * 2)    // 34816 bytes per tile
#define OFF_XH    0
#define OFF_XL    (A_TILE_B)
#define OFF_BHH   (2 * A_TILE_B)
#define OFF_BLL   (3 * A_TILE_B)
#define OFF_BIAS  (4 * A_TILE_B)
#define GEMM_SMEM (OFF_BIAS + 512)

__device__ __forceinline__ void mma16816(float* d, const uint32_t* a, const uint32_t* b)
{
    asm volatile(
        "mma.sync.aligned.m16n8k16.row.col.f32.bf16.bf16.f32 "
        "{%0,%1,%2,%3}, {%4,%5,%6,%7}, {%8,%9}, {%0,%1,%2,%3};"
        : "+f"(d[0]), "+f"(d[1]), "+f"(d[2]), "+f"(d[3])
        : "r"(a[0]), "r"(a[1]), "r"(a[2]), "r"(a[3]), "r"(b[0]), "r"(b[1]));
}

__global__ void __launch_bounds__(256, 1)
gemm_kernel(const float* __restrict__ bq, const float* __restrict__ bk,
            const float* __restrict__ bv, const float* __restrict__ bskip,
            float* __restrict__ out)
{
    extern __shared__ char sm[];
    __nv_bfloat16* Axh = (__nv_bfloat16*)(sm + OFF_XH);
    __nv_bfloat16* Axl = (__nv_bfloat16*)(sm + OFF_XL);
    __nv_bfloat16* Bsh = (__nv_bfloat16*)(sm + OFF_BHH);
    __nv_bfloat16* Bsl = (__nv_bfloat16*)(sm + OFF_BLL);
    float* biasS = (float*)(sm + OFF_BIAS);

    const int tid  = threadIdx.x;
    const int wid  = tid >> 5;
    const int lane = tid & 31;
    const int m0   = blockIdx.x * 128;
    const int y    = blockIdx.y;          // 0=q 1=k 2=v 3=skip
    const int n0   = y * 128;

    // stage A tiles (rows of 128 bf16 = 16 uint4 chunks)
    for (int u = tid; u < 2048; u += 256) {
        int r = u >> 4, c = (u & 15) * 8;
        size_t go = (size_t)(m0 + r) * 128 + c;
        *(uint4*)&Axh[r * PA + c] = *(const uint4*)&g_xh[go];
        *(uint4*)&Axl[r * PA + c] = *(const uint4*)&g_xl[go];
    }
    // stage B tiles: row n (local), k contiguous
    for (int u = tid; u < 2048; u += 256) {
        int r = u >> 4, c = (u & 15) * 8;
        size_t go = (size_t)(n0 + r) * 128 + c;
        *(uint4*)&Bsh[r * PA + c] = *(const uint4*)&g_Bh[go];
        *(uint4*)&Bsl[r * PA + c] = *(const uint4*)&g_Bl[go];
    }
    const float* bsrc = (y == 0) ? bq : (y == 1) ? bk : (y == 2) ? bv : bskip;
    if (tid < 128) biasS[tid] = bsrc[tid];
    __syncthreads();

    const int wm = wid & 3;      // m quadrant (32 rows)
    const int wn = wid >> 2;     // n half (64 cols)
    const int g  = lane >> 2;
    const int t  = lane & 3;

    float acc[2][8][4];
    #pragma unroll
    for (int i = 0; i < 2; i++)
        #pragma unroll
        for (int j = 0; j < 8; j++)
            #pragma unroll
            for (int l = 0; l < 4; l++) acc[i][j][l] = 0.f;

    const __nv_bfloat16* Ap[3] = { Axh, Axl, Axh };
    const __nv_bfloat16* Bp[3] = { Bsh, Bsh, Bsl };

    #pragma unroll
    for (int p = 0; p < 3; p++) {
        const __nv_bfloat16* As = Ap[p];
        const __nv_bfloat16* Bs = Bp[p];
        #pragma unroll
        for (int ks = 0; ks < 8; ks++) {
            const int k0 = ks * 16;
            uint32_t a[2][4], b[8][2];
            #pragma unroll
            for (int mt = 0; mt < 2; mt++) {
                const int rm = wm * 32 + mt * 16 + g;
                a[mt][0] = *(const uint32_t*)&As[rm * PA + k0 + t * 2];
                a[mt][1] = *(const uint32_t*)&As[(rm + 8) * PA + k0 + t * 2];
                a[mt][2] = *(const uint32_t*)&As[rm * PA + k0 + t * 2 + 8];
                a[mt][3] = *(const uint32_t*)&As[(rm + 8) * PA + k0 + t * 2 + 8];
            }
            #pragma unroll
            for (int nt = 0; nt < 8; nt++) {
                const int cn = wn * 64 + nt * 8 + g;
                b[nt][0] = *(const uint32_t*)&Bs[cn * PA + k0 + t * 2];
                b[nt][1] = *(const uint32_t*)&Bs[cn * PA + k0 + t * 2 + 8];
            }
            #pragma unroll
            for (int mt = 0; mt < 2; mt++)
                #pragma unroll
                for (int nt = 0; nt < 8; nt++)
                    mma16816(acc[mt][nt], a[mt], b[nt]);
        }
    }

    // epilogue: direct biased float2 stores
    float* dst = (y == 0) ? g_q : (y == 1) ? g_k : (y == 2) ? g_v : out;
    #pragma unroll
    for (int mt = 0; mt < 2; mt++) {
        const int r0 = m0 + wm * 32 + mt * 16 + g;
        #pragma unroll
        for (int nt = 0; nt < 8; nt++) {
            const int c = wn * 64 + nt * 8 + t * 2;
            const float b0 = biasS[c], b1 = biasS[c + 1];
            if (r0 < NN)
                *(float2*)&dst[(size_t)r0 * 128 + c] =
                    make_float2(acc[mt][nt][0] + b0, acc[mt][nt][1] + b1);
            if (r0 + 8 < NN)
                *(float2*)&dst[(size_t)(r0 + 8) * 128 + c] =
                    make_float2(acc[mt][nt][2] + b0, acc[mt][nt][3] + b1);
        }
    }
}

// ---------------- qWe[n,h,d] = sum_c q[n,h,c] * We[d, h*64+c] ----------------
__global__ void qwe_kernel(const float* __restrict__ We)
{
    __shared__ float WeT[128][33];
    __shared__ float qs[QNB][128];
    const int tid = threadIdx.x;

    for (int idx = tid; idx < 32 * 128; idx += 256) {
        int d  = idx >> 7;
        int hc = idx & 127;
        WeT[hc][d] = We[idx];
    }
    const int n0 = blockIdx.x * QNB;
    for (int idx = tid; idx < QNB * 128; idx += 256) {
        int nl = idx >> 7;
        int n  = n0 + nl;
        qs[nl][idx & 127] = (n < NN) ? g_q[n * HC + (idx & 127)] : 0.f;
    }
    __syncthreads();

    const int d  = tid & 31;
    const int nl = tid >> 5;
    float a0 = 0.f, a1 = 0.f;
    #pragma unroll
    for (int cc = 0; cc < CCH; cc++) {
        a0 += qs[nl][cc]      * WeT[cc][d];
        a1 += qs[nl][64 + cc] * WeT[64 + cc][d];
    }
    const int n = n0 + nl;
    if (n < NN) {
        g_qwe[n * 64 + d]      = a0;
        g_qwe[n * 64 + 32 + d] = a1;
    }
}

// ---------------- CSR build ----------------
__global__ void zero_deg_kernel()
{
    int i = blockIdx.x * blockDim.x + threadIdx.x;
    if (i < NN) g_deg[i] = 0;
}

__global__ void hist_kernel(const int* __restrict__ ei)
{
    int e = blockIdx.x * blockDim.x + threadIdx.x;
    if (e < EE) atomicAdd(&g_deg[ei[EE + e]], 1);
}

__global__ void scan_kernel()
{
    const int tid  = threadIdx.x;
    const int lane = tid & 31;
    const int wid  = tid >> 5;
    __shared__ int wsum[32];
    __shared__ int s_carry;
    if (tid == 0) s_carry = 0;
    __syncthreads();

    for (int base = 0; base < NN; base += 1024) {
        int i = base + tid;
        int v = (i < NN) ? g_deg[i] : 0;

        int x = v;
        #pragma unroll
        for (int o = 1; o < 32; o <<= 1) {
            int y = __shfl_up_sync(0xffffffffu, x, o);
            if (lane >= o) x += y;
        }
        if (lane == 31) wsum[wid] = x;
        __syncthreads();
        if (wid == 0) {
            int s = wsum[lane];
            #pragma unroll
            for (int o = 1; o < 32; o <<= 1) {
                int y = __shfl_up_sync(0xffffffffu, s, o);
                if (lane >= o) s += y;
            }
            wsum[lane] = s;
        }
        __syncthreads();
        int warp_off = (wid > 0) ? wsum[wid - 1] : 0;
        int excl = s_carry + warp_off + x - v;
        if (i < NN) { g_off[i] = excl; g_cur[i] = excl; }
        __syncthreads();
        if (tid == 1023) s_carry += warp_off + x;
        __syncthreads();
    }
    if (tid == 0) g_off[NN] = s_carry;
}

__global__ void scatter_kernel(const int* __restrict__ ei)
{
    int e = blockIdx.x * blockDim.x + threadIdx.x;
    if (e >= EE) return;
    int d = ei[EE + e];
    int p = atomicAdd(&g_cur[d], 1);
    g_srcs[p] = ei[e];
    g_eids[p] = e;
}

// ---------------- aggregation: one warp per destination node ----------------
__global__ void agg_kernel(const float* __restrict__ edge_attr,
                           const float* __restrict__ We,
                           float* __restrict__ out)
{
    const int gw   = (blockIdx.x * blockDim.x + threadIdx.x) >> 5;
    const int lane = threadIdx.x & 31;
    __shared__ float swa[8][64];
    if (gw >= NN) return;
    const int n = gw;

    const int beg = g_off[n];
    const int end = g_off[n + 1];

    const float4 qv = *(const float4*)&g_q[n * HC + lane * 4];
    const float qw0 = g_qwe[n * 64 + lane];
    const float qw1 = g_qwe[n * 64 + 32 + lane];

    float a0 = 0.f, a1 = 0.f, a2 = 0.f, a3 = 0.f;
    float wa0 = 0.f, wa1 = 0.f, den0 = 0.f, den1 = 0.f;

    for (int i = beg; i < end; i++) {
        const int s   = g_srcs[i];
        const int eid = g_eids[i];

        const float4 kv = *(const float4*)&g_k[s * HC + lane * 4];
        float pd = qv.x * kv.x + qv.y * kv.y + qv.z * kv.z + qv.w * kv.w;
        pd += __shfl_xor_sync(0xffffffffu, pd, 8);
        pd += __shfl_xor_sync(0xffffffffu, pd, 4);
        pd += __shfl_xor_sync(0xffffffffu, pd, 2);
        pd += __shfl_xor_sync(0xffffffffu, pd, 1);
        const float dk0 = __shfl_sync(0xffffffffu, pd, 0);
        const float dk1 = __shfl_sync(0xffffffffu, pd, 16);

        const float av = edge_attr[eid * ED + lane];
        float t0 = av * qw0;
        float t1 = av * qw1;
        #pragma unroll
        for (int off = 16; off; off >>= 1) {
            t0 += __shfl_xor_sync(0xffffffffu, t0, off);
            t1 += __shfl_xor_sync(0xffffffffu, t1, off);
        }

        const float s0 = __expf((dk0 + t0) * 0.125f);
        const float s1 = __expf((dk1 + t1) * 0.125f);
        den0 += s0;
        den1 += s1;

        const float4 vv = *(const float4*)&g_v[s * HC + lane * 4];
        const float sh = (lane < 16) ? s0 : s1;
        a0 += sh * vv.x; a1 += sh * vv.y; a2 += sh * vv.z; a3 += sh * vv.w;

        wa0 += s0 * av;
        wa1 += s1 * av;
    }

    const int w = threadIdx.x >> 5;
    swa[w][lane]      = wa0;
    swa[w][32 + lane] = wa1;
    __syncwarp();

    const float den = ((lane < 16) ? den0 : den1) + 1e-16f;
    const float inv = 1.0f / den;

    const int cbase = lane * 4;
    const int hh = lane >> 4;
    const float* wap = &swa[w][hh * 32];
    float accs[4] = { a0, a1, a2, a3 };
    float r[4];
    #pragma unroll
    for (int j = 0; j < 4; j++) {
        const int ccol = cbase + j;
        float ws = 0.f;
        #pragma unroll
        for (int d = 0; d < ED; d++) ws += wap[d] * We[d * HC + ccol];
        r[j] = (accs[j] + ws) * inv;
    }

    float4 o = *(float4*)&out[n * HC + cbase];
    o.x += r[0]; o.y += r[1]; o.z += r[2]; o.w += r[3];
    *(float4*)&out[n * HC + cbase] = o;
}

// ---------------- launch ----------------
extern "C" void kernel_launch(void* const* d_in, const int* in_sizes, int n_in,
                              void* d_out, int out_size)
{
    const float* x     = (const float*)d_in[0];
    const int*   ei    = (const int*)  d_in[1];
    const float* ea    = (const float*)d_in[2];
    const float* Wq    = (const float*)d_in[3];
    const float* bq    = (const float*)d_in[4];
    const float* Wk    = (const float*)d_in[5];
    const float* bk    = (const float*)d_in[6];
    const float* Wv    = (const float*)d_in[7];
    const float* bv    = (const float*)d_in[8];
    const float* We    = (const float*)d_in[9];
    const float* Wskip = (const float*)d_in[10];
    const float* bskip = (const float*)d_in[11];
    float* out = (float*)d_out;

    cudaFuncSetAttribute(gemm_kernel, cudaFuncAttributeMaxDynamicSharedMemorySize, GEMM_SMEM);

    prep_x_kernel<<<(NPAD * 128 + 255) / 256, 256>>>(x);
    prep_w_kernel<<<(512 * 128 + 255) / 256, 256>>>(Wq, Wk, Wv, Wskip);

    dim3 gg(NPAD / 128, 4);
    gemm_kernel<<<gg, 256, GEMM_SMEM>>>(bq, bk, bv, bskip, out);

    qwe_kernel<<<(NN + QNB - 1) / QNB, 256>>>(We);
    zero_deg_kernel<<<(NN + 255) / 256, 256>>>();
    hist_kernel<<<(EE + 255) / 256, 256>>>(ei);
    scan_kernel<<<1, 1024>>>();
    scatter_kernel<<<(EE + 255) / 256, 256>>>(ei);
    agg_kernel<<<(NN * 32 + 255) / 256, 256>>>(ea, We, out);
}